// round 8
// baseline (speedup 1.0000x reference)
#include <cuda_runtime.h>

#define MROWS 16384
#define RR 32
#define NCTA 148
#define NTHR 256
#define TILES 256          // 64 rows each
#define QPAD 68            // padded smem row stride (floats)

// Scratch (device globals: allocation-free rule)
__device__ float g_part[NCTA][RR * RR * 2];   // per-CTA partial Grams
__device__ float g_G[RR * RR * 2];            // reduced Gram
__device__ float g_U[RR * RR * 2];            // R^{-1} (dense, zeros below diag)
__device__ float g_Q1[MROWS * RR * 2];        // intermediate Q after pass 1
__device__ unsigned g_count;                  // zero-init; monotonic arrivals
__device__ unsigned g_release;                // zero-init; monotonic barrier count

// ---------------------------------------------------------------------------
// Software grid barrier (monotonic, graph-replay safe).
// Invariant at every kernel entry/exit: g_count == NCTA * g_release.
// ---------------------------------------------------------------------------
__device__ __forceinline__ void gridbar(unsigned base_r, unsigned idx) {
    __syncthreads();
    if (threadIdx.x == 0) {
        __threadfence();
        unsigned arrived = atomicAdd(&g_count, 1u) + 1u;
        unsigned target = base_r + idx + 1u;
        if (arrived == NCTA * target)
            atomicAdd(&g_release, 1u);
        while (*(volatile unsigned*)&g_release < target)
            __nanosleep(32);
        __threadfence();
    }
    __syncthreads();
}

// ---------------------------------------------------------------------------
// Gram accumulator over the shared tile (64 rows x 32 complex, stride QPAD)
// ---------------------------------------------------------------------------
struct GramAcc {
    float r00, i00, r01, i01, r10, i10, r11, i11;
    __device__ __forceinline__ void zero() {
        r00 = i00 = r01 = i01 = r10 = i10 = r11 = i11 = 0.f;
    }
    __device__ __forceinline__ void accum_tile(const float* s, int bi, int bj) {
        #pragma unroll 8
        for (int m = 0; m < 64; ++m) {
            const float* row = s + m * QPAD;
            float4 ai = *reinterpret_cast<const float4*>(row + 4 * bi);
            float4 aj = *reinterpret_cast<const float4*>(row + 4 * bj);
            r00 += ai.x * aj.x + ai.y * aj.y;
            i00 += ai.x * aj.y - ai.y * aj.x;
            r01 += ai.x * aj.z + ai.y * aj.w;
            i01 += ai.x * aj.w - ai.y * aj.z;
            r10 += ai.z * aj.x + ai.w * aj.y;
            i10 += ai.z * aj.y - ai.w * aj.x;
            r11 += ai.z * aj.z + ai.w * aj.w;
            i11 += ai.z * aj.w - ai.w * aj.z;
        }
    }
    __device__ __forceinline__ void store(float* o, int bi, int bj) {
        int i0 = 2 * bi, j0 = 2 * bj;
        o[((i0    ) * RR + j0    ) * 2 + 0] = r00;
        o[((i0    ) * RR + j0    ) * 2 + 1] = i00;
        o[((i0    ) * RR + j0 + 1) * 2 + 0] = r01;
        o[((i0    ) * RR + j0 + 1) * 2 + 1] = i01;
        o[((i0 + 1) * RR + j0    ) * 2 + 0] = r10;
        o[((i0 + 1) * RR + j0    ) * 2 + 1] = i10;
        o[((i0 + 1) * RR + j0 + 1) * 2 + 0] = r11;
        o[((i0 + 1) * RR + j0 + 1) * 2 + 1] = i11;
    }
};

// reduce 148 partials; 16 leading CTAs, 128 threads each
__device__ __forceinline__ void reduce_partials(int bid, int t) {
    if (bid < 16 && t < 128) {
        int e = bid * 128 + t;
        float a0 = 0.f, a1 = 0.f, a2 = 0.f, a3 = 0.f;
        #pragma unroll 4
        for (int p = 0; p < NCTA; p += 4) {
            a0 += g_part[p    ][e];
            a1 += g_part[p + 1][e];
            a2 += g_part[p + 2][e];
            a3 += g_part[p + 3][e];
        }
        g_G[e] = (a0 + a1) + (a2 + a3);
    }
}

// ---------------------------------------------------------------------------
// Register-resident Cholesky + triangular inverse. Warp 0 of CTA 0 only.
// Lane r holds row r of G (fully unrolled -> compile-time reg indices).
// Right-looking factorization with shuffle broadcast; then forward
// substitution with lane j owning column j of W = L^{-1}.
// Final store (FIXED): lane l writes ROW l of U: U[l][r] = conj(W[r][l]).
// ---------------------------------------------------------------------------
__device__ void cholinv_reg(float* sDinv) {
    const unsigned FULL = 0xffffffffu;
    int lane = threadIdx.x;   // 0..31

    float gre[RR], gim[RR];
    #pragma unroll
    for (int i = 0; i < RR; ++i) {
        float2 v = *reinterpret_cast<const float2*>(g_G + (lane * RR + i) * 2);
        gre[i] = v.x; gim[i] = v.y;
    }

    // ---- right-looking Cholesky; L column k overwrites g[k] ----
    #pragma unroll
    for (int k = 0; k < RR; ++k) {
        float d   = __shfl_sync(FULL, gre[k], k);          // uniform pivot
        float inv = rsqrtf(fmaxf(d, 0.f) + 1e-10f);
        float diagL = d * inv;                              // ~sqrt(d)
        if (lane == 0) sDinv[k] = __frcp_rn(diagL);

        float lre = (lane == k) ? diagL : gre[k] * inv;
        float lim = (lane == k) ? 0.f   : gim[k] * inv;
        gre[k] = lre; gim[k] = lim;                         // save L[:,k]

        #pragma unroll
        for (int j = k + 1; j < RR; ++j) {
            float ljre = __shfl_sync(FULL, lre, j);
            float ljim = __shfl_sync(FULL, lim, j);
            // G[r][j] -= L[r][k] * conj(L[j][k])
            gre[j] -= lre * ljre + lim * ljim;
            gim[j] -= lim * ljre - lre * ljim;
        }
    }
    __syncwarp();

    // ---- forward substitution: lane j owns W[:,j] ----
    float wre[RR], wim[RR];
    #pragma unroll
    for (int r = 0; r < RR; ++r) {
        // s = sum_{i<r} L[r][i] * W[i][j]   (W[i][j]=0 for i<j handles bounds)
        float s0re = 0.f, s0im = 0.f, s1re = 0.f, s1im = 0.f;
        #pragma unroll
        for (int i = 0; i < r; ++i) {
            float Lre = __shfl_sync(FULL, gre[i], r);
            float Lim = __shfl_sync(FULL, gim[i], r);
            if (i & 1) {
                s1re += Lre * wre[i] - Lim * wim[i];
                s1im += Lre * wim[i] + Lim * wre[i];
            } else {
                s0re += Lre * wre[i] - Lim * wim[i];
                s0im += Lre * wim[i] + Lim * wre[i];
            }
        }
        float sre = s0re + s1re, sim = s0im + s1im;
        float dv = sDinv[r];                                // uniform broadcast
        float vre = (lane == r) ? dv  : -dv * sre;
        float vim = (lane == r) ? 0.f : -dv * sim;
        if (lane > r) { vre = 0.f; vim = 0.f; }             // W[r][j]=0 for j>r
        wre[r] = vre; wim[r] = vim;
    }

    // ---- U[l][r] = conj(W[r][l]): lane l writes its own row of U ----
    // (zeros above r<l fall out since wre[r]=0 there; row-strided 8B stores,
    //  8KB total, negligible)
    #pragma unroll
    for (int r = 0; r < RR; ++r) {
        float2 u;
        u.x =  wre[r];
        u.y = -wim[r];
        *reinterpret_cast<float2*>(g_U + (lane * RR + r) * 2) = u;
    }
}

// ---------------------------------------------------------------------------
// The one persistent kernel.
// ---------------------------------------------------------------------------
__global__ __launch_bounds__(NTHR, 1)
void fused_cholqr2(const float* __restrict__ A, float* __restrict__ out) {
    __shared__ float sTile[64 * QPAD];   // tile buffer (~17.4 KB)
    __shared__ float sU[RR * RR * 2];    // U broadcast (8 KB)
    __shared__ float sDinv[RR];          // uniform diag reciprocals

    int t   = threadIdx.x;
    int bid = blockIdx.x;

    __shared__ unsigned s_base;
    if (t == 0) s_base = *(volatile unsigned*)&g_release;
    __syncthreads();
    unsigned base_r = s_base;

    int bi = t >> 4, bj = t & 15;
    int rl = t >> 2, gg = t & 3;

    // ---- Stage 1: Gram of A over my tiles ----
    {
        GramAcc acc; acc.zero();
        for (int tile = bid; tile < TILES; tile += NCTA) {
            __syncthreads();
            const float4* src = reinterpret_cast<const float4*>(A + (size_t)tile * 64 * 64);
            #pragma unroll
            for (int k = 0; k < 4; ++k) {
                int v = t + k * 256;
                int r = v >> 4, c4 = v & 15;
                *reinterpret_cast<float4*>(sTile + r * QPAD + c4 * 4) = src[v];
            }
            __syncthreads();
            acc.accum_tile(sTile, bi, bj);
        }
        acc.store(g_part[bid], bi, bj);
    }
    gridbar(base_r, 0);

    // ---- Stage 2: reduce partials -> G ----
    reduce_partials(bid, t);
    gridbar(base_r, 1);

    // ---- Stage 3: Cholesky + inverse (warp 0 of CTA 0) ----
    if (bid == 0 && t < 32) cholinv_reg(sDinv);
    gridbar(base_r, 2);

    // ---- Stage 4: Q1 = A * U  (+ fused Gram of Q1) ----
    for (int e = t; e < RR * RR * 2; e += NTHR) sU[e] = g_U[e];
    {
        GramAcc acc; acc.zero();
        for (int tile = bid; tile < TILES; tile += NCTA) {
            __syncthreads();   // sU loaded; sTile free
            size_t row = (size_t)tile * 64 + rl;
            const float4* s4 = reinterpret_cast<const float4*>(A + row * 64);
            float a[64];
            #pragma unroll
            for (int k = 0; k < 16; ++k)
                reinterpret_cast<float4*>(a)[k] = s4[k];

            #pragma unroll
            for (int jj = 0; jj < 8; ++jj) {
                int j = 4 * jj + gg;
                float qre = 0.f, qim = 0.f;
                #pragma unroll
                for (int k = 0; k < 4 * jj + 4; ++k) {
                    float2 u = *reinterpret_cast<const float2*>(sU + (k * RR + j) * 2);
                    qre += a[2 * k] * u.x - a[2 * k + 1] * u.y;
                    qim += a[2 * k] * u.y + a[2 * k + 1] * u.x;
                }
                sTile[rl * QPAD + 2 * j]     = qre;
                sTile[rl * QPAD + 2 * j + 1] = qim;
            }
            __syncthreads();

            float4* out4 = reinterpret_cast<float4*>(g_Q1 + (size_t)tile * 64 * 64);
            #pragma unroll
            for (int w = 0; w < 4; ++w) {
                int v = w * 256 + t;
                int rr = v >> 4, c4 = v & 15;
                out4[v] = *reinterpret_cast<const float4*>(sTile + rr * QPAD + c4 * 4);
            }
            acc.accum_tile(sTile, bi, bj);
        }
        acc.store(g_part[bid], bi, bj);
    }
    gridbar(base_r, 3);

    // ---- Stage 5: reduce partials -> G ----
    reduce_partials(bid, t);
    gridbar(base_r, 4);

    // ---- Stage 6: Cholesky + inverse (warp 0 of CTA 0) ----
    if (bid == 0 && t < 32) cholinv_reg(sDinv);
    gridbar(base_r, 5);

    // ---- Stage 7: Q = Q1 * U -> out ----
    for (int e = t; e < RR * RR * 2; e += NTHR) sU[e] = g_U[e];
    for (int tile = bid; tile < TILES; tile += NCTA) {
        __syncthreads();
        size_t row = (size_t)tile * 64 + rl;
        const float4* s4 = reinterpret_cast<const float4*>(g_Q1 + row * 64);
        float a[64];
        #pragma unroll
        for (int k = 0; k < 16; ++k)
            reinterpret_cast<float4*>(a)[k] = s4[k];

        #pragma unroll
        for (int jj = 0; jj < 8; ++jj) {
            int j = 4 * jj + gg;
            float qre = 0.f, qim = 0.f;
            #pragma unroll
            for (int k = 0; k < 4 * jj + 4; ++k) {
                float2 u = *reinterpret_cast<const float2*>(sU + (k * RR + j) * 2);
                qre += a[2 * k] * u.x - a[2 * k + 1] * u.y;
                qim += a[2 * k] * u.y + a[2 * k + 1] * u.x;
            }
            sTile[rl * QPAD + 2 * j]     = qre;
            sTile[rl * QPAD + 2 * j + 1] = qim;
        }
        __syncthreads();

        float4* out4 = reinterpret_cast<float4*>(out + (size_t)tile * 64 * 64);
        #pragma unroll
        for (int w = 0; w < 4; ++w) {
            int v = w * 256 + t;
            int rr = v >> 4, c4 = v & 15;
            out4[v] = *reinterpret_cast<const float4*>(sTile + rr * QPAD + c4 * 4);
        }
    }
}

// ---------------------------------------------------------------------------
extern "C" void kernel_launch(void* const* d_in, const int* in_sizes, int n_in,
                              void* d_out, int out_size) {
    const float* A = (const float*)d_in[0];
    float* out = (float*)d_out;
    fused_cholqr2<<<NCTA, NTHR>>>(A, out);
}

// round 12
// speedup vs baseline: 1.0233x; 1.0233x over previous
#include <cuda_runtime.h>

#define MROWS 16384
#define RR 32
#define NCTA 256
#define NTHR 256
#define QPAD 68            // padded smem row stride (floats)

// Scratch (device globals: allocation-free rule)
__device__ float g_part[NCTA][RR * RR * 2];   // per-CTA partial Grams
__device__ float g_G[RR * RR * 2];            // reduced Gram
__device__ unsigned g_count;                  // zero-init; monotonic arrivals
__device__ unsigned g_release;                // zero-init; monotonic barrier count

// ---------------------------------------------------------------------------
// Software grid barrier (monotonic, graph-replay safe).
// Invariant at every kernel entry/exit: g_count == NCTA * g_release.
// ---------------------------------------------------------------------------
__device__ __forceinline__ void gridbar(unsigned base_r, unsigned idx) {
    __syncthreads();
    if (threadIdx.x == 0) {
        __threadfence();
        unsigned arrived = atomicAdd(&g_count, 1u) + 1u;
        unsigned target = base_r + idx + 1u;
        if (arrived == NCTA * target)
            atomicAdd(&g_release, 1u);
        while (*(volatile unsigned*)&g_release < target)
            __nanosleep(32);
        __threadfence();
    }
    __syncthreads();
}

// ---------------------------------------------------------------------------
// Gram accumulator over the shared tile (64 rows x 32 complex, stride QPAD)
// ---------------------------------------------------------------------------
struct GramAcc {
    float r00, i00, r01, i01, r10, i10, r11, i11;
    __device__ __forceinline__ void zero() {
        r00 = i00 = r01 = i01 = r10 = i10 = r11 = i11 = 0.f;
    }
    __device__ __forceinline__ void accum_tile(const float* s, int bi, int bj) {
        #pragma unroll 8
        for (int m = 0; m < 64; ++m) {
            const float* row = s + m * QPAD;
            float4 ai = *reinterpret_cast<const float4*>(row + 4 * bi);
            float4 aj = *reinterpret_cast<const float4*>(row + 4 * bj);
            r00 += ai.x * aj.x + ai.y * aj.y;
            i00 += ai.x * aj.y - ai.y * aj.x;
            r01 += ai.x * aj.z + ai.y * aj.w;
            i01 += ai.x * aj.w - ai.y * aj.z;
            r10 += ai.z * aj.x + ai.w * aj.y;
            i10 += ai.z * aj.y - ai.w * aj.x;
            r11 += ai.z * aj.z + ai.w * aj.w;
            i11 += ai.z * aj.w - ai.w * aj.z;
        }
    }
    __device__ __forceinline__ void store(float* o, int bi, int bj) {
        int i0 = 2 * bi, j0 = 2 * bj;
        o[((i0    ) * RR + j0    ) * 2 + 0] = r00;
        o[((i0    ) * RR + j0    ) * 2 + 1] = i00;
        o[((i0    ) * RR + j0 + 1) * 2 + 0] = r01;
        o[((i0    ) * RR + j0 + 1) * 2 + 1] = i01;
        o[((i0 + 1) * RR + j0    ) * 2 + 0] = r10;
        o[((i0 + 1) * RR + j0    ) * 2 + 1] = i10;
        o[((i0 + 1) * RR + j0 + 1) * 2 + 0] = r11;
        o[((i0 + 1) * RR + j0 + 1) * 2 + 1] = i11;
    }
};

// reduce NCTA partials; 16 leading CTAs, 128 threads each
__device__ __forceinline__ void reduce_partials(int bid, int t) {
    if (bid < 16 && t < 128) {
        int e = bid * 128 + t;
        float a0 = 0.f, a1 = 0.f, a2 = 0.f, a3 = 0.f;
        #pragma unroll 4
        for (int p = 0; p < NCTA; p += 4) {
            a0 += g_part[p    ][e];
            a1 += g_part[p + 1][e];
            a2 += g_part[p + 2][e];
            a3 += g_part[p + 3][e];
        }
        g_G[e] = (a0 + a1) + (a2 + a3);
    }
}

// ---------------------------------------------------------------------------
// Per-CTA Cholesky + triangular inverse (smem version; low reg pressure).
// Reads g_G, leaves U = R^{-1} (dense, zeros below diag, row-major) in sG.
// All 256 threads must call (internal __syncthreads). Warp 0 factors.
// sL column-major: sL[i*64 + 2r] = L[r][i].  sW row-per-col: sW[i*64+2j]=W[i][j].
// ---------------------------------------------------------------------------
__device__ void cholinv_smem(float* sG, float* sL, float* sW, int t) {
    for (int e = t; e < RR * RR * 2; e += NTHR) {
        sG[e] = g_G[e];
        sL[e] = 0.f;
        sW[e] = 0.f;
    }
    __syncthreads();

    if (t < 32) {
        int r = t;
        for (int k = 0; k < RR; ++k) {
            float sre = sG[(r * RR + k) * 2];
            float sim = sG[(r * RR + k) * 2 + 1];
            for (int i = 0; i < k; ++i) {
                float lr_re = sL[i * 64 + 2 * r], lr_im = sL[i * 64 + 2 * r + 1];
                float lk_re = sL[i * 64 + 2 * k], lk_im = sL[i * 64 + 2 * k + 1];
                sre -= lr_re * lk_re + lr_im * lk_im;
                sim -= lr_im * lk_re - lr_re * lk_im;
            }
            float d   = __shfl_sync(0xffffffffu, sre, k);
            float inv = rsqrtf(fmaxf(d, 0.f) + 1e-10f);
            if (r >= k) {
                sL[k * 64 + 2 * r]     = (r == k) ? (d * inv) : (sre * inv);
                sL[k * 64 + 2 * r + 1] = (r == k) ? 0.f : (sim * inv);
            }
            __syncwarp();
        }
        int j = t;
        sW[j * 64 + 2 * j]     = 1.f / sL[j * 64 + 2 * j];
        sW[j * 64 + 2 * j + 1] = 0.f;
        __syncwarp();
        for (int r2 = 1; r2 < RR; ++r2) {
            if (r2 > j) {
                float sre = 0.f, sim = 0.f;
                for (int i = j; i < r2; ++i) {
                    float l_re = sL[i * 64 + 2 * r2], l_im = sL[i * 64 + 2 * r2 + 1];
                    float w_re = sW[i * 64 + 2 * j],  w_im = sW[i * 64 + 2 * j + 1];
                    sre += l_re * w_re - l_im * w_im;
                    sim += l_re * w_im + l_im * w_re;
                }
                float invd = 1.f / sL[r2 * 64 + 2 * r2];
                sW[r2 * 64 + 2 * j]     = -sre * invd;
                sW[r2 * 64 + 2 * j + 1] = -sim * invd;
            }
            __syncwarp();
        }
    }
    __syncthreads();

    // U[k][j] = conj(W[j][k]) for k <= j, dense, into sG (overwrites dead G)
    for (int e = t; e < RR * RR; e += NTHR) {
        int k = e >> 5, j = e & 31;
        float ure = 0.f, uim = 0.f;
        if (k <= j) {
            ure =  sW[j * 64 + 2 * k];
            uim = -sW[j * 64 + 2 * k + 1];
        }
        sG[2 * e]     = ure;
        sG[2 * e + 1] = uim;
    }
    __syncthreads();
}

// ---------------------------------------------------------------------------
// Triangular multiply on the resident tile: sTile (A or Q1 rows) x sU -> sTile.
// 4 threads per row; thread gg owns columns j = 4*jj + gg.
// ---------------------------------------------------------------------------
__device__ __forceinline__ void qmul_tile(float* sTile, const float* sU,
                                          int rl, int gg) {
    float a[64];
    const float* rowp = sTile + rl * QPAD;
    #pragma unroll
    for (int k = 0; k < 16; ++k)
        reinterpret_cast<float4*>(a)[k] =
            *reinterpret_cast<const float4*>(rowp + 4 * k);
    __syncthreads();   // everyone captured their row; safe to overwrite

    #pragma unroll
    for (int jj = 0; jj < 8; ++jj) {
        int j = 4 * jj + gg;
        float qre = 0.f, qim = 0.f;
        #pragma unroll
        for (int k = 0; k < 4 * jj + 4; ++k) {
            float2 u = *reinterpret_cast<const float2*>(sU + (k * RR + j) * 2);
            qre += a[2 * k] * u.x - a[2 * k + 1] * u.y;
            qim += a[2 * k] * u.y + a[2 * k + 1] * u.x;
        }
        sTile[rl * QPAD + 2 * j]     = qre;
        sTile[rl * QPAD + 2 * j + 1] = qim;
    }
    __syncthreads();
}

// ---------------------------------------------------------------------------
// The one persistent kernel. grid=256 (one 64-row tile per CTA, smem-resident
// for the whole kernel), 2 CTAs/SM.
// ---------------------------------------------------------------------------
__global__ __launch_bounds__(NTHR, 2)
void fused_cholqr2(const float* __restrict__ A, float* __restrict__ out) {
    __shared__ float sTile[64 * QPAD];   // resident tile (~17.4 KB)
    __shared__ float sU[RR * RR * 2];    // G scratch -> U (8 KB)
    __shared__ float sL[RR * RR * 2];    // chol scratch (8 KB)
    __shared__ float sW[RR * RR * 2];    // chol scratch (8 KB)

    int t   = threadIdx.x;
    int bid = blockIdx.x;

    __shared__ unsigned s_base;
    if (t == 0) s_base = *(volatile unsigned*)&g_release;
    __syncthreads();
    unsigned base_r = s_base;

    int bi = t >> 4, bj = t & 15;
    int rl = t >> 2, gg = t & 3;

    // ---- Stage 1: load my tile of A into smem; Gram -> partial ----
    {
        const float4* src = reinterpret_cast<const float4*>(A + (size_t)bid * 64 * 64);
        #pragma unroll
        for (int k = 0; k < 4; ++k) {
            int v = t + k * 256;
            int r = v >> 4, c4 = v & 15;
            *reinterpret_cast<float4*>(sTile + r * QPAD + c4 * 4) = src[v];
        }
        __syncthreads();
        GramAcc acc; acc.zero();
        acc.accum_tile(sTile, bi, bj);
        acc.store(g_part[bid], bi, bj);
    }
    gridbar(base_r, 0);

    // ---- Stage 2: reduce partials -> G ----
    reduce_partials(bid, t);
    gridbar(base_r, 1);

    // ---- Stage 3: every CTA: chol+inv -> sU; Q1 = A*U in place; Gram(Q1) ----
    cholinv_smem(sU, sL, sW, t);
    qmul_tile(sTile, sU, rl, gg);
    {
        GramAcc acc; acc.zero();
        acc.accum_tile(sTile, bi, bj);
        acc.store(g_part[bid], bi, bj);
    }
    gridbar(base_r, 2);

    // ---- Stage 4: reduce partials -> G ----
    reduce_partials(bid, t);
    gridbar(base_r, 3);

    // ---- Stage 5: every CTA: chol+inv -> sU; Q = Q1*U; store out ----
    cholinv_smem(sU, sL, sW, t);
    qmul_tile(sTile, sU, rl, gg);

    float4* out4 = reinterpret_cast<float4*>(out + (size_t)bid * 64 * 64);
    #pragma unroll
    for (int w = 0; w < 4; ++w) {
        int v = w * 256 + t;
        int rr = v >> 4, c4 = v & 15;
        out4[v] = *reinterpret_cast<const float4*>(sTile + rr * QPAD + c4 * 4);
    }
}

// ---------------------------------------------------------------------------
extern "C" void kernel_launch(void* const* d_in, const int* in_sizes, int n_in,
                              void* d_out, int out_size) {
    const float* A = (const float*)d_in[0];
    float* out = (float*)d_out;
    fused_cholqr2<<<NCTA, NTHR>>>(A, out);
}

// round 14
// speedup vs baseline: 1.1182x; 1.0928x over previous
#include <cuda_runtime.h>

#define MROWS 16384
#define RR 32
#define NCTA 256
#define NTHR 256
#define QPAD 68            // padded smem row stride for tiles (floats)
#define UST 66             // sU row stride in floats (33 complex, kills STS conflicts)

// Scratch (device globals: allocation-free rule)
__device__ float g_part[NCTA][RR * RR * 2];   // per-CTA partial Grams
__device__ float g_G[RR * RR * 2];            // reduced Gram
__device__ unsigned g_count;                  // zero-init; monotonic arrivals
__device__ unsigned g_release;                // zero-init; monotonic barrier count

// ---------------------------------------------------------------------------
// Software grid barrier (monotonic, graph-replay safe).
// Invariant at every kernel entry/exit: g_count == NCTA * g_release.
// ---------------------------------------------------------------------------
__device__ __forceinline__ void gridbar(unsigned base_r, unsigned idx) {
    __syncthreads();
    if (threadIdx.x == 0) {
        __threadfence();
        unsigned arrived = atomicAdd(&g_count, 1u) + 1u;
        unsigned target = base_r + idx + 1u;
        if (arrived == NCTA * target)
            atomicAdd(&g_release, 1u);
        while (*(volatile unsigned*)&g_release < target)
            __nanosleep(32);
        __threadfence();
    }
    __syncthreads();
}

// ---------------------------------------------------------------------------
// Gram accumulator over the shared tile (64 rows x 32 complex, stride QPAD)
// ---------------------------------------------------------------------------
struct GramAcc {
    float r00, i00, r01, i01, r10, i10, r11, i11;
    __device__ __forceinline__ void zero() {
        r00 = i00 = r01 = i01 = r10 = i10 = r11 = i11 = 0.f;
    }
    __device__ __forceinline__ void accum_tile(const float* s, int bi, int bj) {
        #pragma unroll 8
        for (int m = 0; m < 64; ++m) {
            const float* row = s + m * QPAD;
            float4 ai = *reinterpret_cast<const float4*>(row + 4 * bi);
            float4 aj = *reinterpret_cast<const float4*>(row + 4 * bj);
            r00 += ai.x * aj.x + ai.y * aj.y;
            i00 += ai.x * aj.y - ai.y * aj.x;
            r01 += ai.x * aj.z + ai.y * aj.w;
            i01 += ai.x * aj.w - ai.y * aj.z;
            r10 += ai.z * aj.x + ai.w * aj.y;
            i10 += ai.z * aj.y - ai.w * aj.x;
            r11 += ai.z * aj.z + ai.w * aj.w;
            i11 += ai.z * aj.w - ai.w * aj.z;
        }
    }
    __device__ __forceinline__ void store(float* o, int bi, int bj) {
        int i0 = 2 * bi, j0 = 2 * bj;
        o[((i0    ) * RR + j0    ) * 2 + 0] = r00;
        o[((i0    ) * RR + j0    ) * 2 + 1] = i00;
        o[((i0    ) * RR + j0 + 1) * 2 + 0] = r01;
        o[((i0    ) * RR + j0 + 1) * 2 + 1] = i01;
        o[((i0 + 1) * RR + j0    ) * 2 + 0] = r10;
        o[((i0 + 1) * RR + j0    ) * 2 + 1] = i10;
        o[((i0 + 1) * RR + j0 + 1) * 2 + 0] = r11;
        o[((i0 + 1) * RR + j0 + 1) * 2 + 1] = i11;
    }
};

// reduce NCTA partials; 16 leading CTAs, 128 threads each
__device__ __forceinline__ void reduce_partials(int bid, int t) {
    if (bid < 16 && t < 128) {
        int e = bid * 128 + t;
        float a0 = 0.f, a1 = 0.f, a2 = 0.f, a3 = 0.f;
        #pragma unroll 4
        for (int p = 0; p < NCTA; p += 4) {
            a0 += g_part[p    ][e];
            a1 += g_part[p + 1][e];
            a2 += g_part[p + 2][e];
            a3 += g_part[p + 3][e];
        }
        g_G[e] = (a0 + a1) + (a2 + a3);
    }
}

// ---------------------------------------------------------------------------
// Fast Cholesky + triangular inverse. Warp 0 only; ~90 live regs (no spill
// under the 128-reg cap from __launch_bounds__(256,2)).
//  Phase 1: rows of G in registers, right-looking, shuffle broadcasts;
//           L column k streamed to sL (column-major: sL[k*64+2r]).
//  Phase 2: forward substitution, lane j owns W[:,j] in registers; L read
//           back via uniform-address LDS.64 broadcasts (pipelined).
//  Output: U[k][j] = conj(W[j][k]) dense rows into sU (row stride UST).
// All 256 threads must call (trailing __syncthreads).
// ---------------------------------------------------------------------------
__device__ void cholinv_fast(float* sU, float* sL, float* sDinv, int t) {
    if (t < 32) {
        const unsigned FULL = 0xffffffffu;
        int lane = t;

        float gre[RR], gim[RR];
        #pragma unroll
        for (int i = 0; i < RR; ++i) {
            float2 v = *reinterpret_cast<const float2*>(g_G + (lane * RR + i) * 2);
            gre[i] = v.x; gim[i] = v.y;
        }

        // ---- right-looking Cholesky; column k -> sL as produced ----
        #pragma unroll
        for (int k = 0; k < RR; ++k) {
            float d   = __shfl_sync(FULL, gre[k], k);
            float inv = rsqrtf(fmaxf(d, 0.f) + 1e-10f);
            float lre = (lane == k) ? (d * inv) : (gre[k] * inv);
            float lim = (lane == k) ? 0.f       : (gim[k] * inv);
            sL[k * 64 + 2 * lane]     = lre;     // conflict-free STS.64
            sL[k * 64 + 2 * lane + 1] = lim;
            if (lane == 0) sDinv[k] = __frcp_rn(d * inv);

            #pragma unroll
            for (int j = k + 1; j < RR; ++j) {
                float ljre = __shfl_sync(FULL, lre, j);
                float ljim = __shfl_sync(FULL, lim, j);
                // G[r][j] -= L[r][k] * conj(L[j][k])
                gre[j] -= lre * ljre + lim * ljim;
                gim[j] -= lim * ljre - lre * ljim;
            }
        }
        __syncwarp();   // all columns of L + sDinv visible across lanes

        // ---- forward substitution: lane j owns W[:,j] ----
        float wre[RR], wim[RR];
        #pragma unroll
        for (int r = 0; r < RR; ++r) {
            float s0re = 0.f, s0im = 0.f, s1re = 0.f, s1im = 0.f;
            #pragma unroll
            for (int i = 0; i < r; ++i) {
                float2 Lv = *reinterpret_cast<const float2*>(sL + i * 64 + 2 * r);
                if (i & 1) {
                    s1re += Lv.x * wre[i] - Lv.y * wim[i];
                    s1im += Lv.x * wim[i] + Lv.y * wre[i];
                } else {
                    s0re += Lv.x * wre[i] - Lv.y * wim[i];
                    s0im += Lv.x * wim[i] + Lv.y * wre[i];
                }
            }
            float sre = s0re + s1re, sim = s0im + s1im;
            float dv = sDinv[r];                     // uniform broadcast
            float vre = (lane == r) ? dv  : -dv * sre;
            float vim = (lane == r) ? 0.f : -dv * sim;
            if (lane > r) { vre = 0.f; vim = 0.f; }  // W upper = 0
            wre[r] = vre; wim[r] = vim;
        }

        // ---- U row `lane`: U[lane][j] = conj(W[j][lane]) = conj(w[j]) ----
        // stride UST=66 floats -> 2-way STS conflicts only
        #pragma unroll
        for (int j = 0; j < RR; ++j) {
            sU[lane * UST + 2 * j]     =  wre[j];
            sU[lane * UST + 2 * j + 1] = -wim[j];
        }
    }
    __syncthreads();
}

// ---------------------------------------------------------------------------
// Triangular multiply on the resident tile: sTile x U -> sTile.
// 4 threads per row; thread gg owns columns j = 4*jj + gg.
// U element (k,j) at sU[k*UST + 2j].
// ---------------------------------------------------------------------------
__device__ __forceinline__ void qmul_tile(float* sTile, const float* sU,
                                          int rl, int gg) {
    float a[64];
    const float* rowp = sTile + rl * QPAD;
    #pragma unroll
    for (int k = 0; k < 16; ++k)
        reinterpret_cast<float4*>(a)[k] =
            *reinterpret_cast<const float4*>(rowp + 4 * k);
    __syncthreads();   // everyone captured their row; safe to overwrite

    #pragma unroll
    for (int jj = 0; jj < 8; ++jj) {
        int j = 4 * jj + gg;
        float qre = 0.f, qim = 0.f;
        #pragma unroll
        for (int k = 0; k < 4 * jj + 4; ++k) {
            float2 u = *reinterpret_cast<const float2*>(sU + k * UST + 2 * j);
            qre += a[2 * k] * u.x - a[2 * k + 1] * u.y;
            qim += a[2 * k] * u.y + a[2 * k + 1] * u.x;
        }
        sTile[rl * QPAD + 2 * j]     = qre;
        sTile[rl * QPAD + 2 * j + 1] = qim;
    }
    __syncthreads();
}

// ---------------------------------------------------------------------------
// The one persistent kernel. grid=256 (one 64-row tile per CTA, smem-resident
// for the whole kernel), 2 CTAs/SM (caps regs at 128 -> no spills).
// ---------------------------------------------------------------------------
__global__ __launch_bounds__(NTHR, 2)
void fused_cholqr2(const float* __restrict__ A, float* __restrict__ out) {
    __shared__ float sTile[64 * QPAD];   // resident tile (~17.4 KB)
    __shared__ float sU[RR * UST];       // U, padded rows (~8.4 KB)
    __shared__ float sL[RR * RR * 2];    // L columns (8 KB)
    __shared__ float sDinv[RR];          // diag reciprocals

    int t   = threadIdx.x;
    int bid = blockIdx.x;

    __shared__ unsigned s_base;
    if (t == 0) s_base = *(volatile unsigned*)&g_release;
    __syncthreads();
    unsigned base_r = s_base;

    int bi = t >> 4, bj = t & 15;
    int rl = t >> 2, gg = t & 3;

    // ---- Stage 1: load my tile of A into smem; Gram -> partial ----
    {
        const float4* src = reinterpret_cast<const float4*>(A + (size_t)bid * 64 * 64);
        #pragma unroll
        for (int k = 0; k < 4; ++k) {
            int v = t + k * 256;
            int r = v >> 4, c4 = v & 15;
            *reinterpret_cast<float4*>(sTile + r * QPAD + c4 * 4) = src[v];
        }
        __syncthreads();
        GramAcc acc; acc.zero();
        acc.accum_tile(sTile, bi, bj);
        acc.store(g_part[bid], bi, bj);
    }
    gridbar(base_r, 0);

    // ---- Stage 2: reduce partials -> G ----
    reduce_partials(bid, t);
    gridbar(base_r, 1);

    // ---- Stage 3: chol+inv -> sU; Q1 = A*U in place; Gram(Q1) ----
    cholinv_fast(sU, sL, sDinv, t);
    qmul_tile(sTile, sU, rl, gg);
    {
        GramAcc acc; acc.zero();
        acc.accum_tile(sTile, bi, bj);
        acc.store(g_part[bid], bi, bj);
    }
    gridbar(base_r, 2);

    // ---- Stage 4: reduce partials -> G ----
    reduce_partials(bid, t);
    gridbar(base_r, 3);

    // ---- Stage 5: chol+inv -> sU; Q = Q1*U; store out ----
    cholinv_fast(sU, sL, sDinv, t);
    qmul_tile(sTile, sU, rl, gg);

    float4* out4 = reinterpret_cast<float4*>(out + (size_t)bid * 64 * 64);
    #pragma unroll
    for (int w = 0; w < 4; ++w) {
        int v = w * 256 + t;
        int rr = v >> 4, c4 = v & 15;
        out4[v] = *reinterpret_cast<const float4*>(sTile + rr * QPAD + c4 * 4);
    }
}

// ---------------------------------------------------------------------------
extern "C" void kernel_launch(void* const* d_in, const int* in_sizes, int n_in,
                              void* d_out, int out_size) {
    const float* A = (const float*)d_in[0];
    float* out = (float*)d_out;
    fused_cholqr2<<<NCTA, NTHR>>>(A, out);
}